// round 1
// baseline (speedup 1.0000x reference)
#include <cuda_runtime.h>

// ---------------------------------------------------------------------------
// Problem constants
// ---------------------------------------------------------------------------
#define BSZ   1024
#define TLEN  64
#define SDIM  30
#define DDIM  200
#define HDIM  200
#define EDIM  1024
#define ADIM  6

// ---------------------------------------------------------------------------
// Device scratch (no cudaMalloc allowed)
// ---------------------------------------------------------------------------
__device__ float g_eo[(size_t)BSZ * TLEN * HDIM];              // embed @ w_obs1_e + b_obs1

// Packed (k-pair interleaved) weights: element [kp][c] is a 64-bit pair
// (w[2kp][c], w[2kp+1][c]) so inner loops can use fma.rn.f32x2.
__device__ unsigned long long g_gru_wp[100 * 600];
__device__ unsigned long long g_gru_up[100 * 600];
__device__ unsigned long long g_wimg1_p[18 * 200];
__device__ unsigned long long g_wimg2_p[100 * 200];
__device__ unsigned long long g_wobs1d_p[100 * 200];
__device__ unsigned long long g_whp[4 * 100 * 30];             // heads: omean, ostd, imean, istd

// ---------------------------------------------------------------------------
// Helpers
// ---------------------------------------------------------------------------
typedef unsigned long long ull;

__device__ __forceinline__ ull fma2(ull a, ull b, ull c) {
    ull d;
    asm("fma.rn.f32x2 %0, %1, %2, %3;" : "=l"(d) : "l"(a), "l"(b), "l"(c));
    return d;
}
__device__ __forceinline__ float sum2(ull a) {
    float2 f;
    asm("mov.b64 {%0, %1}, %2;" : "=f"(f.x), "=f"(f.y) : "l"(a));
    return f.x + f.y;
}
__device__ __forceinline__ float elu1(float v) {
    return v > 0.f ? v : (__expf(v) - 1.f);
}
__device__ __forceinline__ float softplus1(float x) {
    return fmaxf(x, 0.f) + log1pf(__expf(-fabsf(x)));
}
__device__ __forceinline__ float sigmoid1(float x) {
    return 1.f / (1.f + __expf(-x));
}

// ---------------------------------------------------------------------------
// Prologue: repack weights into k-pair interleaved layout
// ---------------------------------------------------------------------------
__global__ void repack_kernel(const float* __restrict__ w_img1,
                              const float* __restrict__ gru_w,
                              const float* __restrict__ gru_u,
                              const float* __restrict__ w_img2,
                              const float* __restrict__ w_obs1,
                              const float* __restrict__ w_omean,
                              const float* __restrict__ w_ostd,
                              const float* __restrict__ w_imean,
                              const float* __restrict__ w_istd) {
    int i = blockIdx.x * blockDim.x + threadIdx.x;
    if (i >= 351200) return;
    if (i < 120000) {
        int p = i & 1, t = i >> 1, c = t % 600, kp = t / 600;
        ((float*)g_gru_wp)[i] = gru_w[(2 * kp + p) * 600 + c];
    } else if (i < 240000) {
        int j = i - 120000;
        int p = j & 1, t = j >> 1, c = t % 600, kp = t / 600;
        ((float*)g_gru_up)[j] = gru_u[(2 * kp + p) * 600 + c];
    } else if (i < 247200) {
        int j = i - 240000;
        int p = j & 1, t = j >> 1, c = t % 200, kp = t / 200;
        ((float*)g_wimg1_p)[j] = w_img1[(2 * kp + p) * 200 + c];
    } else if (i < 287200) {
        int j = i - 247200;
        int p = j & 1, t = j >> 1, c = t % 200, kp = t / 200;
        ((float*)g_wimg2_p)[j] = w_img2[(2 * kp + p) * 200 + c];
    } else if (i < 327200) {
        int j = i - 287200;
        int p = j & 1, t = j >> 1, c = t % 200, kp = t / 200;
        ((float*)g_wobs1d_p)[j] = w_obs1[(2 * kp + p) * 200 + c];  // deter rows 0..199
    } else {
        int j = i - 327200;
        int p = j & 1, t = j >> 1;
        int s = t % 30, u = t / 30, kp = u % 100, h = u / 100;
        const float* src = (h == 0) ? w_omean : (h == 1) ? w_ostd : (h == 2) ? w_imean : w_istd;
        ((float*)g_whp)[j] = src[(2 * kp + p) * 30 + s];
    }
}

// ---------------------------------------------------------------------------
// Kernel 1: g_eo[m][c] = embed_row(m) @ w_obs1[200:1224, :] + b_obs1
// M = 65536 (m = b*64 + t), K = 1024, N = 200
// BM=64, BN=200, BK=32, 320 threads, thread tile 8 rows x 5 cols, f32x2 over k
// ---------------------------------------------------------------------------
__global__ __launch_bounds__(320, 1)
void eo_gemm_kernel(const float* __restrict__ embed,
                    const float* __restrict__ w_obs1,
                    const float* __restrict__ b_obs1) {
    __shared__ __align__(16) float as_f[64 * 32];     // [row][k]
    __shared__ __align__(16) float ws_f[32 * 200];    // packed pairs: [(k/2)*200 + c]*2 + (k&1)

    const ull* as_u = (const ull*)as_f;
    const ull* ws_u = (const ull*)ws_f;

    int tid = threadIdx.x;
    int tx = tid % 40;        // col group (5 cols)
    int ty = tid / 40;        // row group (8 rows)
    int m0 = blockIdx.x * 64;

    ull acc[8][5];
#pragma unroll
    for (int r = 0; r < 8; r++)
#pragma unroll
        for (int j = 0; j < 5; j++) acc[r][j] = 0ull;

    for (int k0 = 0; k0 < 1024; k0 += 32) {
        __syncthreads();
        for (int idx = tid; idx < 2048; idx += 320) {
            int r = idx >> 5, k = idx & 31;
            as_f[idx] = embed[(size_t)(m0 + r) * 1024 + k0 + k];
        }
        for (int idx = tid; idx < 6400; idx += 320) {
            int k = idx / 200, c = idx % 200;
            ws_f[((k >> 1) * 200 + c) * 2 + (k & 1)] =
                w_obs1[(size_t)(200 + k0 + k) * 200 + c];
        }
        __syncthreads();
#pragma unroll
        for (int kp = 0; kp < 16; kp++) {
            ull wv[5];
#pragma unroll
            for (int j = 0; j < 5; j++) wv[j] = ws_u[kp * 200 + tx * 5 + j];
#pragma unroll
            for (int r = 0; r < 8; r++) {
                ull av = as_u[(ty * 8 + r) * 16 + kp];
#pragma unroll
                for (int j = 0; j < 5; j++) acc[r][j] = fma2(av, wv[j], acc[r][j]);
            }
        }
    }

#pragma unroll
    for (int r = 0; r < 8; r++) {
        int m = m0 + ty * 8 + r;
#pragma unroll
        for (int j = 0; j < 5; j++) {
            int c = tx * 5 + j;
            g_eo[(size_t)m * 200 + c] = sum2(acc[r][j]) + b_obs1[c];
        }
    }
}

// ---------------------------------------------------------------------------
// Kernel 2: persistent recurrent kernel.
// 128 CTAs x 8 batch rows, 256 threads, T=64 internal loop.
// ---------------------------------------------------------------------------
__global__ __launch_bounds__(256, 1)
void rssm_recur_kernel(const float* __restrict__ action,
                       const float* __restrict__ noise_prior,
                       const float* __restrict__ noise_post,
                       const float* __restrict__ b_img1,
                       const float* __restrict__ gru_b,
                       const float* __restrict__ gru_rb,
                       const float* __restrict__ b_img2,
                       const float* __restrict__ b_imean,
                       const float* __restrict__ b_istd,
                       const float* __restrict__ b_omean,
                       const float* __restrict__ b_ostd,
                       float* __restrict__ out) {
    __shared__ __align__(16) float sm[11520];
    float* s_in = sm;            // [8][40]  stoch(30) + action(6) + pad
    float* det0 = sm + 320;      // [8][200]
    float* s_x  = sm + 1920;     // [8][200] img1 out; reused as x2 in P4/P5
    float* s_zr = sm + 3520;     // [8][400] z/r pre-activations (P2/P3)
    float* s_xo = sm + 3520;     // [8][200] alias, used in P4/P5
    float* s_hd = sm + 5120;     // [4][8][30] head results (P5/P6)
    float* s_xh = sm + 6720;     // [8][200]
    float* s_hh = sm + 8320;     // [8][200]
    float* det1 = sm + 9920;     // [8][200]

    const int tid = threadIdx.x;
    const int b0 = blockIdx.x * 8;
    const int c = tid;

    for (int i = tid; i < 320; i += 256) s_in[i] = 0.f;
    for (int i = tid; i < 1600; i += 256) det0[i] = 0.f;

    float* pd = det0;   // current deter
    float* pn = det1;   // next deter
    __syncthreads();

    for (int t = 0; t < TLEN; ++t) {
        // ---- P0: load action for step t ----
        if (tid < 48) {
            int r = tid / 6, j = tid % 6;
            s_in[r * 40 + 30 + j] = action[(size_t)(b0 + r) * (TLEN * ADIM) + t * ADIM + j];
        }
        __syncthreads();

        // ---- P1: x = elu([stoch, action] @ w_img1 + b_img1) ----
        if (c < 200) {
            ull acc[8];
#pragma unroll
            for (int r = 0; r < 8; r++) acc[r] = 0ull;
#pragma unroll
            for (int kp = 0; kp < 18; kp++) {
                ull w = __ldg(&g_wimg1_p[kp * 200 + c]);
#pragma unroll
                for (int r = 0; r < 8; r++) {
                    ull in2 = *reinterpret_cast<const ull*>(s_in + r * 40 + 2 * kp);
                    acc[r] = fma2(in2, w, acc[r]);
                }
            }
            float bb = b_img1[c];
#pragma unroll
            for (int r = 0; r < 8; r++) {
                s_x[r * 200 + c] = elu1(sum2(acc[r]) + bb);
            }
        }
        __syncthreads();

        // ---- P2: GRU pre-activations ----
        if (c < 200) {
            ull az[8], ar[8], axh[8], ahh[8];
#pragma unroll
            for (int r = 0; r < 8; r++) { az[r] = 0; ar[r] = 0; axh[r] = 0; ahh[r] = 0; }
            const ull* pw = g_gru_wp + c;
            const ull* pu = g_gru_up + c;
#pragma unroll 2
            for (int kp = 0; kp < 100; kp++) {
                ull wz = __ldg(pw + kp * 600);
                ull uz = __ldg(pu + kp * 600);
                ull wr = __ldg(pw + kp * 600 + 200);
                ull ur = __ldg(pu + kp * 600 + 200);
                ull wh = __ldg(pw + kp * 600 + 400);
                ull uh = __ldg(pu + kp * 600 + 400);
#pragma unroll
                for (int r = 0; r < 8; r++) {
                    ull x2 = *reinterpret_cast<const ull*>(s_x + r * 200 + 2 * kp);
                    ull d2 = *reinterpret_cast<const ull*>(pd + r * 200 + 2 * kp);
                    az[r]  = fma2(x2, wz, az[r]);
                    az[r]  = fma2(d2, uz, az[r]);
                    ar[r]  = fma2(x2, wr, ar[r]);
                    ar[r]  = fma2(d2, ur, ar[r]);
                    axh[r] = fma2(x2, wh, axh[r]);
                    ahh[r] = fma2(d2, uh, ahh[r]);
                }
            }
            float bz  = gru_b[c] + gru_rb[c];
            float br  = gru_b[200 + c] + gru_rb[200 + c];
            float bxh = gru_b[400 + c];
            float bhh = gru_rb[400 + c];
#pragma unroll
            for (int r = 0; r < 8; r++) {
                s_zr[r * 400 + c]       = sum2(az[r]) + bz;
                s_zr[r * 400 + 200 + c] = sum2(ar[r]) + br;
                s_xh[r * 200 + c]       = sum2(axh[r]) + bxh;
                s_hh[r * 200 + c]       = sum2(ahh[r]) + bhh;
            }
        }
        __syncthreads();

        // ---- P3: gates, deter_n; write deter_n to output ----
        for (int idx = tid; idx < 1600; idx += 256) {
            int r = idx / 200, cc = idx - r * 200;
            float z  = sigmoid1(s_zr[r * 400 + cc]);
            float rg = sigmoid1(s_zr[r * 400 + 200 + cc]);
            float a  = s_xh[idx] + rg * s_hh[idx];
            float e2 = __expf(2.f * a);
            float hh = 1.f - 2.f / (e2 + 1.f);
            float dn = z * pd[idx] + (1.f - z) * hh;
            pn[idx] = dn;
            float* orow = out + ((size_t)(b0 + r) * TLEN + t) * 580;
            orow[90 + cc]  = dn;
            orow[380 + cc] = dn;
        }
        __syncthreads();

        // ---- P4: x2 = elu(dn @ w_img2 + b), xo = elu(dn @ w_obs1_d + eo) ----
        if (c < 200) {
            ull aa[8], ab[8];
#pragma unroll
            for (int r = 0; r < 8; r++) { aa[r] = 0; ab[r] = 0; }
            const ull* pa = g_wimg2_p + c;
            const ull* pb = g_wobs1d_p + c;
#pragma unroll 2
            for (int kp = 0; kp < 100; kp++) {
                ull wa = __ldg(pa + kp * 200);
                ull wb = __ldg(pb + kp * 200);
#pragma unroll
                for (int r = 0; r < 8; r++) {
                    ull d2 = *reinterpret_cast<const ull*>(pn + r * 200 + 2 * kp);
                    aa[r] = fma2(d2, wa, aa[r]);
                    ab[r] = fma2(d2, wb, ab[r]);
                }
            }
            float b2 = b_img2[c];
#pragma unroll
            for (int r = 0; r < 8; r++) {
                s_x[r * 200 + c] = elu1(sum2(aa[r]) + b2);  // x2
                float eo = g_eo[((size_t)(b0 + r) * TLEN + t) * 200 + c];
                s_xo[r * 200 + c] = elu1(sum2(ab[r]) + eo); // xo (eo already has b_obs1)
            }
        }
        __syncthreads();

        // ---- P5: 4 heads (omean, ostd, imean, istd) ----
        if (tid < 120) {
            int h = tid / 30, s = tid - h * 30;
            const ull* wp = g_whp + h * 3000 + s;
            const float* src = (h < 2) ? s_xo : s_x;
            ull acc[8];
#pragma unroll
            for (int r = 0; r < 8; r++) acc[r] = 0ull;
#pragma unroll 2
            for (int kp = 0; kp < 100; kp++) {
                ull w = __ldg(wp + kp * 30);
#pragma unroll
                for (int r = 0; r < 8; r++) {
                    ull v2 = *reinterpret_cast<const ull*>(src + r * 200 + 2 * kp);
                    acc[r] = fma2(v2, w, acc[r]);
                }
            }
            float bias = (h == 0) ? b_omean[s] : (h == 1) ? b_ostd[s]
                       : (h == 2) ? b_imean[s] : b_istd[s];
#pragma unroll
            for (int r = 0; r < 8; r++) {
                float v = sum2(acc[r]) + bias;
                float* orow = out + ((size_t)(b0 + r) * TLEN + t) * 580;
                float res;
                if (h == 0)      { res = v;                    orow[s]        = res; }
                else if (h == 1) { res = softplus1(v);         orow[30 + s]   = res; }
                else if (h == 2) { res = v;                    orow[290 + s]  = res; }
                else             { res = softplus1(v) + 0.1f;  orow[320 + s]  = res; }
                s_hd[h * 240 + r * 30 + s] = res;
            }
        }
        __syncthreads();

        // ---- P6: stoch samples, carry update ----
        if (tid < 240) {
            int r = tid / 30, s = tid - r * 30;
            size_t nidx = (size_t)t * (BSZ * SDIM) + (size_t)(b0 + r) * SDIM + s;
            float om  = s_hd[r * 30 + s];
            float osd = s_hd[240 + r * 30 + s];
            float ost = om + osd * noise_post[nidx];
            float pm  = s_hd[480 + r * 30 + s];
            float psd = s_hd[720 + r * 30 + s];
            float pst = pm + psd * noise_prior[nidx];
            float* orow = out + ((size_t)(b0 + r) * TLEN + t) * 580;
            orow[60 + s]  = ost;
            orow[350 + s] = pst;
            s_in[r * 40 + s] = ost;   // stoch carry = posterior sample
        }

        // swap deter buffers
        { float* tmp = pd; pd = pn; pn = tmp; }
        __syncthreads();
    }
}

// ---------------------------------------------------------------------------
// Launch
// ---------------------------------------------------------------------------
extern "C" void kernel_launch(void* const* d_in, const int* in_sizes, int n_in,
                              void* d_out, int out_size) {
    const float* embed       = (const float*)d_in[0];
    const float* action      = (const float*)d_in[1];
    const float* noise_prior = (const float*)d_in[2];
    const float* noise_post  = (const float*)d_in[3];
    const float* w_img1      = (const float*)d_in[4];
    const float* b_img1      = (const float*)d_in[5];
    const float* gru_w       = (const float*)d_in[6];
    const float* gru_u       = (const float*)d_in[7];
    const float* gru_b       = (const float*)d_in[8];
    const float* gru_rb      = (const float*)d_in[9];
    const float* w_img2      = (const float*)d_in[10];
    const float* b_img2      = (const float*)d_in[11];
    const float* w_imean     = (const float*)d_in[12];
    const float* b_imean     = (const float*)d_in[13];
    const float* w_istd      = (const float*)d_in[14];
    const float* b_istd      = (const float*)d_in[15];
    const float* w_obs1      = (const float*)d_in[16];
    const float* b_obs1      = (const float*)d_in[17];
    const float* w_omean     = (const float*)d_in[18];
    const float* b_omean     = (const float*)d_in[19];
    const float* w_ostd      = (const float*)d_in[20];
    const float* b_ostd      = (const float*)d_in[21];
    float* out = (float*)d_out;

    repack_kernel<<<(351200 + 255) / 256, 256>>>(w_img1, gru_w, gru_u, w_img2, w_obs1,
                                                 w_omean, w_ostd, w_imean, w_istd);
    eo_gemm_kernel<<<BSZ * TLEN / 64, 320>>>(embed, w_obs1, b_obs1);
    rssm_recur_kernel<<<BSZ / 8, 256>>>(action, noise_prior, noise_post,
                                        b_img1, gru_b, gru_rb, b_img2,
                                        b_imean, b_istd, b_omean, b_ostd, out);
}